// round 9
// baseline (speedup 1.0000x reference)
#include <cuda_runtime.h>
#include <cstdint>

#define NN 64
#define C1 128
#define C2 256
#define H1 56
#define W1 56
#define H2 28
#define W2 28
#define HW1 (H1*W1)        // 3136
#define HW2 (H2*W2)        // 784
#define NPIX (NN*HW2)      // 50176
#define TOT2 (NN*C2*HW2)   // 12845056

// ---------------- scratch (static device globals; no runtime allocation) ----------------
__device__ uint4 g_xb[NN*H1*W1];     // packed sign(x): [n][h][w], 128 ch -> 4 words
__device__ uint4 g_w1b[C2*9];        // packed sign(w1): [co][tap], 128 ch -> 4 words
__device__ uint4 g_w2b[C2*9*2];      // packed sign(w2): [co][tap][2], 256 ch -> 8 words
__device__ uint4 g_wsb[C2];          // packed sign(ws): [co], 128 ch -> 4 words
__device__ uint4 g_o1b[NPIX*2];      // packed sign(BN1 out): [n][oh][ow][2]
__device__ short g_t1[TOT2];         // conv1 integer dot (pre-scale, pre-BN1)
__device__ float g_part[3*128];      // partial |w| sums (t*128 + blk)
__device__ float g_A1[C2], g_B1[C2]; // BN1 binarize affine: sign(A1*I + B1)
__device__ float g_A2[C2], g_B2[C2]; // BN2 normalize affine: v*A2 + B2

// ---------------- |w| partial sums (stage 1 of alpha; finalize folded downstream) ----------------
__global__ void k_abs_partial(const float* __restrict__ w1, const float* __restrict__ w2,
                              const float* __restrict__ ws) {
    int t = blockIdx.y;
    const float* s = (t == 0) ? w1 : ((t == 1) ? w2 : ws);
    int n = (t == 0) ? C2*C1*9 : ((t == 1) ? C2*C2*9 : C2*C1);
    float acc = 0.f;
    for (int i = blockIdx.x*blockDim.x + threadIdx.x; i < n; i += gridDim.x*blockDim.x)
        acc += fabsf(s[i]);
    __shared__ float sh[256];
    sh[threadIdx.x] = acc; __syncthreads();
    for (int o = 128; o > 0; o >>= 1) {
        if (threadIdx.x < o) sh[threadIdx.x] += sh[threadIdx.x + o];
        __syncthreads();
    }
    if (threadIdx.x == 0) g_part[t*128 + blockIdx.x] = sh[0];
}

// ---------------- pack weight sign bits ----------------
__global__ void k_pack_w(const float* __restrict__ w1, const float* __restrict__ w2,
                         const float* __restrict__ ws) {
    int idx = blockIdx.x*blockDim.x + threadIdx.x;
    if (idx < C2*9*4) {
        int co = idx/36, rem = idx%36, tap = rem/4, wd = rem%4;
        unsigned b = 0;
        for (int j = 0; j < 32; j++) {
            float v = w1[(co*C1 + wd*32 + j)*9 + tap];
            b |= (v >= 0.f ? 1u : 0u) << j;
        }
        ((unsigned*)g_w1b)[(co*9 + tap)*4 + wd] = b;
    } else if (idx < C2*9*4 + C2*9*8) {
        int k = idx - C2*9*4;
        int co = k/72, rem = k%72, tap = rem/8, wd = rem%8;
        unsigned b = 0;
        for (int j = 0; j < 32; j++) {
            float v = w2[(co*C2 + wd*32 + j)*9 + tap];
            b |= (v >= 0.f ? 1u : 0u) << j;
        }
        ((unsigned*)g_w2b)[(co*9 + tap)*8 + wd] = b;
    } else if (idx < C2*9*4 + C2*9*8 + C2*4) {
        int k = idx - (C2*9*4 + C2*9*8);
        int co = k/4, wd = k%4;
        unsigned b = 0;
        for (int j = 0; j < 32; j++) {
            float v = ws[co*C1 + wd*32 + j];
            b |= (v >= 0.f ? 1u : 0u) << j;
        }
        ((unsigned*)g_wsb)[co*4 + wd] = b;
    }
}

// ---------------- pack sign(x) along channels ----------------
__global__ void k_pack_x(const float* __restrict__ x) {
    int p = blockIdx.x*blockDim.x + threadIdx.x;
    if (p >= NN*HW1) return;
    int n = p / HW1, hw = p - n*HW1;
    const unsigned* xu = (const unsigned*)x;
    unsigned wd[4];
    #pragma unroll
    for (int q = 0; q < 4; q++) {
        unsigned b = 0;
        #pragma unroll 8
        for (int j = 0; j < 32; j++) {
            unsigned u = xu[(n*C1 + q*32 + j)*HW1 + hw];
            b |= ((~u) >> 31) << j;    // 1 iff sign bit clear (v >= 0)
        }
        wd[q] = b;
    }
    g_xb[p] = make_uint4(wd[0], wd[1], wd[2], wd[3]);
}

// ---------------- conv1: 3x3 s2 p1; 2 rows/block, co-half per z, x read from smem ----------------
__global__ void __launch_bounds__(224, 4) k_conv1() {
    int oh0 = blockIdx.x * 2, n = blockIdx.y, coh = blockIdx.z;
    __shared__ uint4 sin_[5*W1];        // rows ih = 2*oh0-1 .. 2*oh0+3   (4480 B)
    __shared__ uint4 sw[128*9];         // co half                        (18432 B)
    for (int i = threadIdx.x; i < 5*W1; i += 224) {
        int r = i / W1, c = i - r*W1;
        int ih = 2*oh0 - 1 + r;
        if (ih >= 0) sin_[i] = g_xb[(n*H1 + ih)*W1 + c];
    }
    for (int i = threadIdx.x; i < 128*9; i += 224) sw[i] = g_w1b[coh*128*9 + i];
    __syncthreads();
    int ow = threadIdx.x % 28;
    int cog = threadIdx.x / 28;
    #pragma unroll
    for (int rr = 0; rr < 2; rr++) {
        int oh = oh0 + rr;
        unsigned vm[9]; int idx9[9]; int nval = 0;
        #pragma unroll
        for (int kh = 0; kh < 3; kh++)
            #pragma unroll
            for (int kw = 0; kw < 3; kw++) {
                int t = kh*3 + kw;
                int ih = 2*oh - 1 + kh, iw = 2*ow - 1 + kw;
                bool v = (ih >= 0) && (iw >= 0);
                vm[t] = v ? 0xFFFFFFFFu : 0u; nval += v ? 1 : 0;
                int iwc = iw < 0 ? 0 : iw;
                idx9[t] = (2*rr + kh)*W1 + iwc;
            }
        int base = 128 * nval;
        int obase = ((n*C2 + coh*128)*H2 + oh)*W2 + ow;
        for (int i = 0; i < 16; i++) {
            int col = cog*16 + i;
            const uint4* wp = &sw[col*9];
            int p0 = 0, p1 = 0, p2 = 0, p3 = 0;
            #pragma unroll
            for (int t = 0; t < 9; t++) {
                uint4 w = wp[t]; uint4 xv = sin_[idx9[t]]; unsigned m = vm[t];
                p0 += __popc((xv.x ^ w.x) & m);
                p1 += __popc((xv.y ^ w.y) & m);
                p2 += __popc((xv.z ^ w.z) & m);
                p3 += __popc((xv.w ^ w.w) & m);
            }
            int pop = (p0 + p1) + (p2 + p3);
            g_t1[obase + col*HW2] = (short)(base - 2*pop);
        }
    }
}

// ---------------- BN1 stats (exact int accumulation, uint4 loads) + alpha1 finalize ----------------
__global__ void __launch_bounds__(512) k_stats1(const float* __restrict__ g1,
                                                const float* __restrict__ b1) {
    __shared__ float s_a1;
    int tid = threadIdx.x;
    if (tid < 32) {
        float v = g_part[tid] + g_part[tid+32] + g_part[tid+64] + g_part[tid+96];
        #pragma unroll
        for (int o = 16; o > 0; o >>= 1) v += __shfl_xor_sync(0xFFFFFFFFu, v, o);
        if (tid == 0) s_a1 = v / (float)(C2*C1*9);
    }
    int co = blockIdx.x;
    int s = 0; long long s2 = 0;
    // 8 shorts per uint4; HW2=784 shorts = 98 uint4 per image
    for (int j = tid; j < NN*98; j += 512) {
        int n = j / 98, r = (j - n*98);
        const uint4 u = ((const uint4*)&g_t1[(n*C2 + co)*HW2])[r];
        #pragma unroll
        for (int k = 0; k < 4; k++) {
            unsigned w = (&u.x)[k];
            int v0 = (int)(short)(w & 0xFFFFu);
            int v1 = (int)(short)(w >> 16);
            s += v0 + v1;
            s2 += (long long)(v0*v0 + v1*v1);
        }
    }
    __shared__ int sa[512]; __shared__ long long sb[512];
    sa[tid] = s; sb[tid] = s2; __syncthreads();
    for (int o = 256; o > 0; o >>= 1) {
        if (tid < o) { sa[tid] += sa[tid+o]; sb[tid] += sb[tid+o]; }
        __syncthreads();
    }
    if (tid == 0) {
        double a1 = (double)s_a1;
        double mi  = (double)sa[0] / (double)NPIX;
        double vi  = (double)sb[0] / (double)NPIX - mi*mi;
        float rs = (float)(1.0 / sqrt(a1*a1*vi + 1e-5));
        float mus = (float)(a1 * mi);
        float gc = g1[co];
        g_A1[co] = (float)a1 * rs * gc;
        g_B1[co] = b1[co] - mus * rs * gc;
    }
}

// ---------------- binarize+pack BN1 output: smem transpose + ballot ----------------
__global__ void __launch_bounds__(256) k_pack_o1() {
    __shared__ int   sarr[C2*33];
    __shared__ float shA[C2], shB[C2];
    int tid = threadIdx.x, wq = tid >> 5, lane = tid & 31;
    int tidx = blockIdx.x, n = blockIdx.y;
    int hw0 = tidx * 32;
    int P = (hw0 + 32 <= HW2) ? 32 : (HW2 - hw0);
    if (tid < C2) { shA[tid] = g_A1[tid]; shB[tid] = g_B1[tid]; }
    for (int c = wq; c < C2; c += 8) {
        if (lane < P)
            sarr[c*33 + lane] = (int)g_t1[(n*C2 + c)*HW2 + hw0 + lane];
    }
    __syncthreads();
    int ch = wq*32 + lane;
    float A = shA[ch], B = shB[ch];
    unsigned myword = 0;
    for (int px = 0; px < P; px++) {
        float o = fmaf(A, (float)sarr[ch*33 + px], B);
        unsigned w = __ballot_sync(0xFFFFFFFFu, o >= 0.f);
        if (lane == px) myword = w;
    }
    if (lane < P)
        ((unsigned*)g_o1b)[(n*HW2 + hw0 + lane)*8 + wq] = myword;
}

// ---------------- conv2 (3x3 s1 p1) + 1x1 shortcut; 2 rows/block, x from smem ----------------
__global__ void __launch_bounds__(224, 4) k_conv2(float* __restrict__ out) {
    int oh0 = blockIdx.x * 2, n = blockIdx.y, coh = blockIdx.z;
    __shared__ uint4 sin_[4*W2*2];      // rows ih = oh0-1 .. oh0+2   (3584 B)
    __shared__ uint4 sw[128*18];        // 36864 B
    __shared__ uint4 sws[128];          // 2048 B
    __shared__ float s_a2, s_as;
    int tid = threadIdx.x;
    for (int i = tid; i < 4*W2*2; i += 224) {
        int r = i / (W2*2); int rem = i - r*(W2*2);
        int ih = oh0 - 1 + r;
        if (ih >= 0 && ih < H2) sin_[i] = g_o1b[((n*H2 + ih)*W2)*2 + rem];
    }
    for (int i = tid; i < 128*18; i += 224) sw[i] = g_w2b[coh*128*18 + i];
    if (tid < 128) sws[tid] = g_wsb[coh*128 + tid];
    if (tid < 32) {
        float v2 = g_part[128+tid] + g_part[160+tid] + g_part[192+tid] + g_part[224+tid];
        float vs = g_part[256+tid] + g_part[288+tid] + g_part[320+tid] + g_part[352+tid];
        #pragma unroll
        for (int o = 16; o > 0; o >>= 1) {
            v2 += __shfl_xor_sync(0xFFFFFFFFu, v2, o);
            vs += __shfl_xor_sync(0xFFFFFFFFu, vs, o);
        }
        if (tid == 0) { s_a2 = v2 / (float)(C2*C2*9); s_as = vs / (float)(C2*C1); }
    }
    __syncthreads();
    int ow = tid % 28, cog = tid / 28;
    float a2 = s_a2, as_ = s_as;
    #pragma unroll
    for (int rr = 0; rr < 2; rr++) {
        int oh = oh0 + rr;
        unsigned vm[9]; int idx9[9]; int nval = 0;
        #pragma unroll
        for (int kh = 0; kh < 3; kh++)
            #pragma unroll
            for (int kw = 0; kw < 3; kw++) {
                int t = kh*3 + kw;
                int ih = oh - 1 + kh, iw = ow - 1 + kw;
                bool v = ((unsigned)ih < H2) && ((unsigned)iw < W2);
                vm[t] = v ? 0xFFFFFFFFu : 0u; nval += v ? 1 : 0;
                int iwc = iw < 0 ? 0 : (iw > W2-1 ? W2-1 : iw);
                idx9[t] = ((rr + kh)*W2 + iwc)*2;
            }
        uint4 xs = g_xb[(n*H1 + 2*oh)*W1 + 2*ow];
        float base = 256.f * (float)nval;
        int obase = ((n*C2 + coh*128)*H2 + oh)*W2 + ow;
        for (int i = 0; i < 16; i++) {
            int col = cog*16 + i;
            const uint4* wp = &sw[col*18];
            int p0 = 0, p1 = 0, p2 = 0, p3 = 0;
            #pragma unroll
            for (int t = 0; t < 9; t++) {
                uint4 wa = wp[2*t], wb = wp[2*t + 1]; unsigned m = vm[t];
                uint4 va = sin_[idx9[t]], vb = sin_[idx9[t] + 1];
                p0 += __popc((va.x ^ wa.x) & m) + __popc((vb.x ^ wb.x) & m);
                p1 += __popc((va.y ^ wa.y) & m) + __popc((vb.y ^ wb.y) & m);
                p2 += __popc((va.z ^ wa.z) & m) + __popc((vb.z ^ wb.z) & m);
                p3 += __popc((va.w ^ wa.w) & m) + __popc((vb.w ^ wb.w) & m);
            }
            int pop = (p0 + p1) + (p2 + p3);
            uint4 wv = sws[col];
            int ps = __popc(xs.x ^ wv.x) + __popc(xs.y ^ wv.y)
                   + __popc(xs.z ^ wv.z) + __popc(xs.w ^ wv.w);
            out[obase + col*HW2] = fmaf(a2, base - 2.f*(float)pop, as_ * (128.f - 2.f*(float)ps));
        }
    }
}

// ---------------- BN2 stats: float4 loads, f32 per-thread, double block tree ----------------
__global__ void __launch_bounds__(512) k_stats2(const float* __restrict__ out,
                                                const float* __restrict__ g2,
                                                const float* __restrict__ b2) {
    int co = blockIdx.x;
    float s = 0.f, s2 = 0.f;
    // 784 floats = 196 float4 per image row
    for (int j = threadIdx.x; j < NN*196; j += 512) {
        int n = j / 196, r = j - n*196;
        float4 v = ((const float4*)&out[(n*C2 + co)*HW2])[r];
        s += (v.x + v.y) + (v.z + v.w);
        s2 = fmaf(v.x, v.x, fmaf(v.y, v.y, fmaf(v.z, v.z, fmaf(v.w, v.w, s2))));
    }
    __shared__ double sa[512], sb[512];
    sa[threadIdx.x] = (double)s; sb[threadIdx.x] = (double)s2; __syncthreads();
    for (int o = 256; o > 0; o >>= 1) {
        if (threadIdx.x < o) { sa[threadIdx.x] += sa[threadIdx.x+o]; sb[threadIdx.x] += sb[threadIdx.x+o]; }
        __syncthreads();
    }
    if (threadIdx.x == 0) {
        double m = sa[0] / (double)NPIX;
        double var = sb[0] / (double)NPIX - m*m;
        float rs = (float)(1.0 / sqrt(var + 1e-5));
        float mus = (float)m;
        float gc = g2[co];
        g_A2[co] = rs * gc;
        g_B2[co] = b2[co] - mus * rs * gc;
    }
}

// ---------------- final BN2 normalize (in-place, float4) ----------------
__global__ void k_norm(float* __restrict__ out) {
    int i = blockIdx.x*blockDim.x + threadIdx.x;   // float4 index
    if (i >= TOT2/4) return;
    int c = (i / (HW2/4)) & (C2 - 1);
    float A = g_A2[c], B = g_B2[c];
    float4 v = ((float4*)out)[i];
    v.x = fmaf(v.x, A, B); v.y = fmaf(v.y, A, B);
    v.z = fmaf(v.z, A, B); v.w = fmaf(v.w, A, B);
    ((float4*)out)[i] = v;
}

// ---------------- launch ----------------
extern "C" void kernel_launch(void* const* d_in, const int* in_sizes, int n_in,
                              void* d_out, int out_size) {
    const float* x  = (const float*)d_in[0];
    const float* w1 = (const float*)d_in[1];
    const float* g1 = (const float*)d_in[2];
    const float* b1 = (const float*)d_in[3];
    const float* w2 = (const float*)d_in[4];
    const float* g2 = (const float*)d_in[5];
    const float* b2 = (const float*)d_in[6];
    const float* ws = (const float*)d_in[7];
    float* out = (float*)d_out;

    k_abs_partial<<<dim3(128, 3), 256>>>(w1, w2, ws);
    k_pack_w<<<112, 256>>>(w1, w2, ws);
    k_pack_x<<<(NN*HW1 + 255)/256, 256>>>(x);
    k_conv1<<<dim3(14, NN, 2), 224>>>();
    k_stats1<<<C2, 512>>>(g1, b1);
    k_pack_o1<<<dim3(25, NN), 256>>>();
    k_conv2<<<dim3(14, NN, 2), 224>>>(out);
    k_stats2<<<C2, 512>>>(out, g2, b2);
    k_norm<<<(TOT2/4 + 255)/256, 256>>>(out);
}

// round 10
// speedup vs baseline: 1.0278x; 1.0278x over previous
#include <cuda_runtime.h>
#include <cstdint>

#define NN 64
#define C1 128
#define C2 256
#define H1 56
#define W1 56
#define H2 28
#define W2 28
#define HW1 (H1*W1)        // 3136
#define HW2 (H2*W2)        // 784
#define NPIX (NN*HW2)      // 50176
#define TOT2 (NN*C2*HW2)   // 12845056

// ---------------- scratch (static device globals; no runtime allocation) ----------------
__device__ uint4 g_xb[NN*HW1];       // packed sign(x): [n][h][w], 128 ch -> 4 words
__device__ uint4 g_w1b[9*C2];        // packed sign(w1): [tap][co]  (tap-major for coalesced reg fill)
__device__ uint4 g_w2b[9*2*C2];      // packed sign(w2): [tap][half][co]
__device__ uint4 g_wsb[C2];          // packed sign(ws): [co]
__device__ unsigned g_o1b[8*NPIX];   // packed sign(BN1 out): [q][n*HW2+hw]
__device__ short g_t1[NPIX*C2];      // conv1 integer dot: [pix][co]  (TRANSPOSED)
__device__ float g_part[3*128];      // partial |w| sums (t*128 + blk)
__device__ int g_s1p[98*C2];         // BN1 stats partials: sum
__device__ int g_s1q[98*C2];         // BN1 stats partials: sum of squares
__device__ float g_A1[C2], g_B1[C2]; // BN1 binarize affine: sign(A1*I + B1)
__device__ float g_A2[C2], g_B2[C2]; // BN2 normalize affine: v*A2 + B2

// ---------------- |w| partial sums ----------------
__global__ void k_abs_partial(const float* __restrict__ w1, const float* __restrict__ w2,
                              const float* __restrict__ ws) {
    int t = blockIdx.y;
    const float* s = (t == 0) ? w1 : ((t == 1) ? w2 : ws);
    int n = (t == 0) ? C2*C1*9 : ((t == 1) ? C2*C2*9 : C2*C1);
    float acc = 0.f;
    for (int i = blockIdx.x*blockDim.x + threadIdx.x; i < n; i += gridDim.x*blockDim.x)
        acc += fabsf(s[i]);
    __shared__ float sh[256];
    sh[threadIdx.x] = acc; __syncthreads();
    for (int o = 128; o > 0; o >>= 1) {
        if (threadIdx.x < o) sh[threadIdx.x] += sh[threadIdx.x + o];
        __syncthreads();
    }
    if (threadIdx.x == 0) g_part[t*128 + blockIdx.x] = sh[0];
}

// ---------------- pack weight sign bits (tap-major layouts) ----------------
__global__ void k_pack_w(const float* __restrict__ w1, const float* __restrict__ w2,
                         const float* __restrict__ ws) {
    int idx = blockIdx.x*blockDim.x + threadIdx.x;
    if (idx < C2*9*4) {
        int co = idx/36, rem = idx%36, tap = rem/4, wd = rem%4;
        unsigned b = 0;
        for (int j = 0; j < 32; j++) {
            float v = w1[(co*C1 + wd*32 + j)*9 + tap];
            b |= (v >= 0.f ? 1u : 0u) << j;
        }
        ((unsigned*)g_w1b)[(tap*C2 + co)*4 + wd] = b;
    } else if (idx < C2*9*4 + C2*9*8) {
        int k = idx - C2*9*4;
        int co = k/72, rem = k%72, tap = rem/8, wd = rem%8;
        unsigned b = 0;
        for (int j = 0; j < 32; j++) {
            float v = w2[(co*C2 + wd*32 + j)*9 + tap];
            b |= (v >= 0.f ? 1u : 0u) << j;
        }
        ((unsigned*)g_w2b)[((tap*2 + (wd>>2))*C2 + co)*4 + (wd&3)] = b;
    } else if (idx < C2*9*4 + C2*9*8 + C2*4) {
        int k = idx - (C2*9*4 + C2*9*8);
        int co = k/4, wd = k%4;
        unsigned b = 0;
        for (int j = 0; j < 32; j++) {
            float v = ws[co*C1 + wd*32 + j];
            b |= (v >= 0.f ? 1u : 0u) << j;
        }
        ((unsigned*)g_wsb)[co*4 + wd] = b;
    }
}

// ---------------- pack sign(x) along channels ----------------
__global__ void k_pack_x(const float* __restrict__ x) {
    int p = blockIdx.x*blockDim.x + threadIdx.x;
    if (p >= NN*HW1) return;
    int n = p / HW1, hw = p - n*HW1;
    const unsigned* xu = (const unsigned*)x;
    unsigned wd[4];
    #pragma unroll
    for (int q = 0; q < 4; q++) {
        unsigned b = 0;
        #pragma unroll 8
        for (int j = 0; j < 32; j++) {
            unsigned u = xu[(n*C1 + q*32 + j)*HW1 + hw];
            b |= ((~u) >> 31) << j;
        }
        wd[q] = b;
    }
    g_xb[p] = make_uint4(wd[0], wd[1], wd[2], wd[3]);
}

// ---------------- conv1: thread = out channel, weights in regs, x broadcast from smem ----------------
__global__ void __launch_bounds__(256, 3) k_conv1() {
    int oh = blockIdx.x, n = blockIdx.y;
    __shared__ uint4 sx[3*W1];          // rows ih = 2oh-1, 2oh, 2oh+1
    int tid = threadIdx.x;
    for (int i = tid; i < 3*W1; i += 256) {
        int r = i / W1, c = i - r*W1;
        int ih = 2*oh - 1 + r;
        if (ih >= 0) sx[i] = g_xb[(n*H1 + ih)*W1 + c];
    }
    uint4 w[9];
    #pragma unroll
    for (int t = 0; t < 9; t++) w[t] = g_w1b[t*C2 + tid];   // coalesced
    __syncthreads();
    int obase = (n*HW2 + oh*W2)*C2 + tid;
    for (int ow = 0; ow < W2; ow++) {
        int p0 = 0, p1 = 0, p2 = 0, p3 = 0, nval = 0;
        #pragma unroll
        for (int kh = 0; kh < 3; kh++) {
            #pragma unroll
            for (int kw = 0; kw < 3; kw++) {
                int t = kh*3 + kw;
                int ih = 2*oh - 1 + kh, iw = 2*ow - 1 + kw;
                bool v = (ih >= 0) && (iw >= 0);
                unsigned m = v ? 0xFFFFFFFFu : 0u;
                nval += v ? 1 : 0;
                uint4 xv = sx[kh*W1 + (iw < 0 ? 0 : iw)];   // broadcast LDS
                p0 += __popc((xv.x ^ w[t].x) & m);
                p1 += __popc((xv.y ^ w[t].y) & m);
                p2 += __popc((xv.z ^ w[t].z) & m);
                p3 += __popc((xv.w ^ w[t].w) & m);
            }
        }
        int pop = (p0 + p1) + (p2 + p3);
        g_t1[obase + ow*C2] = (short)(128*nval - 2*pop);    // coalesced 512B store
    }
}

// ---------------- BN1 stats stage A: per-pixel-chunk int partials (exact) ----------------
__global__ void __launch_bounds__(256) k_stats1a() {
    int tid = threadIdx.x;
    int p0 = blockIdx.x * 512;
    int s = 0, s2 = 0;                  // s2 max 512*1152^2 = 679M < 2^31
    #pragma unroll 4
    for (int p = p0; p < p0 + 512; p++) {
        int v = (int)g_t1[p*C2 + tid];  // coalesced 64B/warp
        s += v; s2 += v*v;
    }
    g_s1p[blockIdx.x*C2 + tid] = s;
    g_s1q[blockIdx.x*C2 + tid] = s2;
}

// ---------------- BN1 stats stage B: finalize A1/B1 (+ alpha1 reduce) ----------------
__global__ void __launch_bounds__(256) k_stats1b(const float* __restrict__ g1,
                                                 const float* __restrict__ b1) {
    __shared__ float sh[128];
    int tid = threadIdx.x;
    if (tid < 128) sh[tid] = g_part[tid];
    __syncthreads();
    for (int o = 64; o > 0; o >>= 1) { if (tid < o) sh[tid] += sh[tid+o]; __syncthreads(); }
    float a1f = sh[0] / (float)(C2*C1*9);
    long long S = 0, S2 = 0;
    for (int b = 0; b < 98; b++) {
        S  += (long long)g_s1p[b*C2 + tid];
        S2 += (long long)g_s1q[b*C2 + tid];
    }
    double a1 = (double)a1f;
    double mi = (double)S  / (double)NPIX;
    double vi = (double)S2 / (double)NPIX - mi*mi;
    float rs  = (float)(1.0 / sqrt(a1*a1*vi + 1e-5));
    float mus = (float)(a1 * mi);
    float gc = g1[tid];
    g_A1[tid] = a1f * rs * gc;
    g_B1[tid] = b1[tid] - mus * rs * gc;
}

// ---------------- binarize+pack BN1 output: coalesced loads + ballot, q-major store ----------------
__global__ void __launch_bounds__(256) k_pack_o1() {
    int tid = threadIdx.x, wq = tid >> 5, lane = tid & 31;
    int p0 = blockIdx.x * 32;
    float A = g_A1[tid], B = g_B1[tid];
    unsigned myword = 0;
    #pragma unroll 4
    for (int i = 0; i < 32; i++) {
        int v = (int)g_t1[(p0 + i)*C2 + tid];   // coalesced 64B/warp
        float o = fmaf(A, (float)v, B);
        unsigned w = __ballot_sync(0xFFFFFFFFu, o >= 0.f);
        if (lane == i) myword = w;
    }
    g_o1b[wq*NPIX + p0 + lane] = myword;        // coalesced 128B/warp
}

// ---------------- conv2 + 1x1 shortcut: thread = out channel, weights in regs ----------------
__global__ void __launch_bounds__(256, 2) k_conv2(float* __restrict__ out) {
    int oh = blockIdx.x, n = blockIdx.y;
    __shared__ uint4 sxq[3*W2*2];       // [(r*W2+iw)*2 + half], 8 words per input pixel
    __shared__ uint4 sxs[W2];           // shortcut packed x per ow
    __shared__ float sres[C2*29];       // padded stride 29: conflict-free
    __shared__ float s_a2, s_as;
    int tid = threadIdx.x;
    // fill input taps (q-interleaved into uint4 pairs)
    for (int i = tid; i < 3*W2*8; i += 256) {
        int q = i & 7; int rem = i >> 3; int iw = rem % W2, r = rem / W2;
        int ih = oh - 1 + r;
        ((unsigned*)sxq)[(r*W2 + iw)*8 + q] =
            (ih >= 0 && ih < H2) ? g_o1b[q*NPIX + n*HW2 + ih*W2 + iw] : 0u;
    }
    if (tid < W2) sxs[tid] = g_xb[(n*H1 + 2*oh)*W1 + 2*tid];
    uint4 wa[9], wb[9];
    #pragma unroll
    for (int t = 0; t < 9; t++) {
        wa[t] = g_w2b[(t*2 + 0)*C2 + tid];      // coalesced
        wb[t] = g_w2b[(t*2 + 1)*C2 + tid];
    }
    uint4 wv = g_wsb[tid];
    if (tid < 32) {
        float v2 = g_part[128+tid] + g_part[160+tid] + g_part[192+tid] + g_part[224+tid];
        float vs = g_part[256+tid] + g_part[288+tid] + g_part[320+tid] + g_part[352+tid];
        #pragma unroll
        for (int o = 16; o > 0; o >>= 1) {
            v2 += __shfl_xor_sync(0xFFFFFFFFu, v2, o);
            vs += __shfl_xor_sync(0xFFFFFFFFu, vs, o);
        }
        if (tid == 0) { s_a2 = v2 / (float)(C2*C2*9); s_as = vs / (float)(C2*C1); }
    }
    __syncthreads();
    float a2 = s_a2, as_ = s_as;
    for (int ow = 0; ow < W2; ow++) {
        int p0 = 0, p1 = 0, p2 = 0, p3 = 0, nval = 0;
        #pragma unroll
        for (int kh = 0; kh < 3; kh++) {
            #pragma unroll
            for (int kw = 0; kw < 3; kw++) {
                int t = kh*3 + kw;
                int ih = oh - 1 + kh, iw = ow - 1 + kw;
                bool v = ((unsigned)ih < H2) && ((unsigned)iw < W2);
                unsigned m = v ? 0xFFFFFFFFu : 0u;
                nval += v ? 1 : 0;
                int iwc = iw < 0 ? 0 : (iw > W2-1 ? W2-1 : iw);
                uint4 lo = sxq[(kh*W2 + iwc)*2];        // broadcast LDS
                uint4 hi = sxq[(kh*W2 + iwc)*2 + 1];
                p0 += __popc((lo.x ^ wa[t].x) & m) + __popc((hi.x ^ wb[t].x) & m);
                p1 += __popc((lo.y ^ wa[t].y) & m) + __popc((hi.y ^ wb[t].y) & m);
                p2 += __popc((lo.z ^ wa[t].z) & m) + __popc((hi.z ^ wb[t].z) & m);
                p3 += __popc((lo.w ^ wa[t].w) & m) + __popc((hi.w ^ wb[t].w) & m);
            }
        }
        int pop = (p0 + p1) + (p2 + p3);
        uint4 xs = sxs[ow];
        int ps = __popc(xs.x ^ wv.x) + __popc(xs.y ^ wv.y)
               + __popc(xs.z ^ wv.z) + __popc(xs.w ^ wv.w);
        sres[tid*29 + ow] = fmaf(a2, (float)(256*nval - 2*pop), as_ * (float)(128 - 2*ps));
    }
    __syncthreads();
    int ob = (n*C2)*HW2 + oh*W2;
    for (int i = tid; i < C2*W2; i += 256) {
        int col = i / W2, px = i - col*W2;
        out[ob + col*HW2 + px] = sres[col*29 + px];
    }
}

// ---------------- BN2 stats: float4 loads, f32 per-thread, double block tree ----------------
__global__ void __launch_bounds__(512) k_stats2(const float* __restrict__ out,
                                                const float* __restrict__ g2,
                                                const float* __restrict__ b2) {
    int co = blockIdx.x;
    float s = 0.f, s2 = 0.f;
    for (int j = threadIdx.x; j < NN*196; j += 512) {
        int n = j / 196, r = j - n*196;
        float4 v = ((const float4*)&out[(n*C2 + co)*HW2])[r];
        s += (v.x + v.y) + (v.z + v.w);
        s2 = fmaf(v.x, v.x, fmaf(v.y, v.y, fmaf(v.z, v.z, fmaf(v.w, v.w, s2))));
    }
    __shared__ double sa[512], sb[512];
    sa[threadIdx.x] = (double)s; sb[threadIdx.x] = (double)s2; __syncthreads();
    for (int o = 256; o > 0; o >>= 1) {
        if (threadIdx.x < o) { sa[threadIdx.x] += sa[threadIdx.x+o]; sb[threadIdx.x] += sb[threadIdx.x+o]; }
        __syncthreads();
    }
    if (threadIdx.x == 0) {
        double m = sa[0] / (double)NPIX;
        double var = sb[0] / (double)NPIX - m*m;
        float rs = (float)(1.0 / sqrt(var + 1e-5));
        float mus = (float)m;
        float gc = g2[co];
        g_A2[co] = rs * gc;
        g_B2[co] = b2[co] - mus * rs * gc;
    }
}

// ---------------- final BN2 normalize (in-place, float4) ----------------
__global__ void k_norm(float* __restrict__ out) {
    int i = blockIdx.x*blockDim.x + threadIdx.x;
    if (i >= TOT2/4) return;
    int c = (i / (HW2/4)) & (C2 - 1);
    float A = g_A2[c], B = g_B2[c];
    float4 v = ((float4*)out)[i];
    v.x = fmaf(v.x, A, B); v.y = fmaf(v.y, A, B);
    v.z = fmaf(v.z, A, B); v.w = fmaf(v.w, A, B);
    ((float4*)out)[i] = v;
}

// ---------------- launch ----------------
extern "C" void kernel_launch(void* const* d_in, const int* in_sizes, int n_in,
                              void* d_out, int out_size) {
    const float* x  = (const float*)d_in[0];
    const float* w1 = (const float*)d_in[1];
    const float* g1 = (const float*)d_in[2];
    const float* b1 = (const float*)d_in[3];
    const float* w2 = (const float*)d_in[4];
    const float* g2 = (const float*)d_in[5];
    const float* b2 = (const float*)d_in[6];
    const float* ws = (const float*)d_in[7];
    float* out = (float*)d_out;

    k_abs_partial<<<dim3(128, 3), 256>>>(w1, w2, ws);
    k_pack_w<<<112, 256>>>(w1, w2, ws);
    k_pack_x<<<(NN*HW1 + 255)/256, 256>>>(x);
    k_conv1<<<dim3(H2, NN), 256>>>();
    k_stats1a<<<98, 256>>>();
    k_stats1b<<<1, 256>>>(g1, b1);
    k_pack_o1<<<NPIX/32, 256>>>();
    k_conv2<<<dim3(H2, NN), 256>>>(out);
    k_stats2<<<C2, 512>>>(out, g2, b2);
    k_norm<<<(TOT2/4 + 255)/256, 256>>>(out);
}